// round 1
// baseline (speedup 1.0000x reference)
#include <cuda_runtime.h>
#include <cuda_bf16.h>

// Trilinear interpolation: 300000 vertices, vol (1,16,112,224,160) f32.
// Output: (1, 300000, 16) f32  (reference returns out.T[None]).
//
// One thread per vertex. Channel loop inside thread: the 4 (x,y) corner base
// addresses + 8 trilinear weights are computed once; per channel we issue
// 8 loads (4 float-pairs at z0/z1). Accumulate 16 results in registers,
// store with 4x float4 (STG.128).

#define D1 112
#define D2 224
#define D3 160
#define NC 16
#define NVERT 300000
#define EPSV 1e-5f

__global__ __launch_bounds__(256) void lerp3d_kernel(
    const float* __restrict__ vert,   // [NVERT, 3]
    const float* __restrict__ vol,    // [NC, D1, D2, D3]
    float* __restrict__ out)          // [NVERT, NC]
{
    int i = blockIdx.x * blockDim.x + threadIdx.x;
    if (i >= NVERT) return;

    // Load vertex coords
    float vx = vert[3 * i + 0];
    float vy = vert[3 * i + 1];
    float vz = vert[3 * i + 2];

    // Clip to [EPS, dim-1-EPS]
    vx = fminf(fmaxf(vx, EPSV), (float)D1 - 1.0f - EPSV);
    vy = fminf(fmaxf(vy, EPSV), (float)D2 - 1.0f - EPSV);
    vz = fminf(fmaxf(vz, EPSV), (float)D3 - 1.0f - EPSV);

    float fx = floorf(vx);
    float fy = floorf(vy);
    float fz = floorf(vz);

    float ux = vx - fx;
    float uy = vy - fy;
    float uz = vz - fz;

    int x0 = (int)fx;
    int y0 = (int)fy;
    int z0 = (int)fz;

    // Trilinear weights (z handled by pairing z0/z1 loads)
    float oux = 1.0f - ux;
    float ouy = 1.0f - uy;
    float ouz = 1.0f - uz;

    float w00 = oux * ouy;   // (x0, y0)
    float w01 = oux * uy;    // (x0, y1)
    float w10 = ux  * ouy;   // (x1, y0)
    float w11 = ux  * uy;    // (x1, y1)

    // Base offsets for the 4 (x,y) corners at z0. z1 = z0+1 (contiguous).
    const long sX = (long)D2 * D3;     // 35840
    const long sY = (long)D3;          // 160
    const long sC = (long)D1 * D2 * D3; // 4014080

    long b00 = (long)x0 * sX + (long)y0 * sY + z0;
    long b01 = b00 + sY;        // y1
    long b10 = b00 + sX;        // x1
    long b11 = b10 + sY;        // x1,y1

    float res[NC];

    #pragma unroll
    for (int c = 0; c < NC; c++) {
        const float* V = vol + (long)c * sC;
        // 8 corner loads: 4 contiguous pairs (z0, z0+1)
        float a0 = __ldg(V + b00);
        float a1 = __ldg(V + b00 + 1);
        float b0 = __ldg(V + b01);
        float b1 = __ldg(V + b01 + 1);
        float c0 = __ldg(V + b10);
        float c1 = __ldg(V + b10 + 1);
        float d0 = __ldg(V + b11);
        float d1 = __ldg(V + b11 + 1);

        // blend over x,y first (weights), then z
        float lo = w00 * a0 + w01 * b0 + w10 * c0 + w11 * d0;  // z0 plane
        float hi = w00 * a1 + w01 * b1 + w10 * c1 + w11 * d1;  // z1 plane

        res[c] = lo * ouz + hi * uz;
    }

    // 4x float4 stores (out row is 64B, 16B-aligned)
    float4* o4 = reinterpret_cast<float4*>(out + (long)i * NC);
    o4[0] = make_float4(res[0],  res[1],  res[2],  res[3]);
    o4[1] = make_float4(res[4],  res[5],  res[6],  res[7]);
    o4[2] = make_float4(res[8],  res[9],  res[10], res[11]);
    o4[3] = make_float4(res[12], res[13], res[14], res[15]);
}

extern "C" void kernel_launch(void* const* d_in, const int* in_sizes, int n_in,
                              void* d_out, int out_size) {
    const float* vert = (const float*)d_in[0];  // (1, 300000, 3)
    const float* vol  = (const float*)d_in[1];  // (1, 16, 112, 224, 160)
    float* out = (float*)d_out;                 // (1, 300000, 16)

    const int threads = 256;
    const int blocks = (NVERT + threads - 1) / threads;
    lerp3d_kernel<<<blocks, threads>>>(vert, vol, out);
}

// round 2
// speedup vs baseline: 1.2036x; 1.2036x over previous
#include <cuda_runtime.h>
#include <cuda_bf16.h>

// Trilinear interpolation, two-phase:
//   1) transpose vol (16,112,224,160) channel-major -> volT (112,224,160,16)
//      channels-last, so each (x,y,z0/z1) corner-pair is one contiguous,
//      64B-aligned 128B block (16ch @ z0 + 16ch @ z1), 100% useful bytes.
//   2) gather: one thread per vertex, 4 corner-pair blocks of 8x float4.
//
// DRAM traffic: ~514MB transpose + ~177MB gather vs ~1.44GB for the naive
// channel-major gather.

#define D1 112
#define D2 224
#define D3 160
#define NC 16
#define NVERT 300000
#define EPSV 1e-5f

// 257 MB scratch (allowed: __device__ global, not a runtime allocation)
__device__ float g_volT[(size_t)D1 * D2 * D3 * NC];

// ---------------- transpose: vol[c][x][y][z] -> volT[x][y][z][c] -------------
// One block per (x,y) row: slab is [16][160] -> [160][16].
// smem padded to stride 161 floats: conflict-free on both phases.
__global__ __launch_bounds__(256) void transpose_kernel(
    const float* __restrict__ vol)
{
    __shared__ float s[NC * (D3 + 1)];

    int xy = blockIdx.x;            // 0 .. D1*D2-1
    const long sC = (long)D1 * D2 * D3;
    long base_in = (long)xy * D3;   // == (x*D2 + y)*D3

    // Phase 1: coalesced reads along z, write smem [c][z] padded
    for (int idx = threadIdx.x; idx < NC * D3; idx += blockDim.x) {
        int c = idx / D3;
        int z = idx - c * D3;
        s[c * (D3 + 1) + z] = vol[(long)c * sC + base_in + z];
    }
    __syncthreads();

    // Phase 2: coalesced writes, contiguous [z][c]
    float* outp = g_volT + base_in * NC;
    for (int idx = threadIdx.x; idx < NC * D3; idx += blockDim.x) {
        int z = idx >> 4;           // idx / 16
        int c = idx & 15;           // idx % 16
        outp[idx] = s[c * (D3 + 1) + z];
    }
}

// ---------------- gather ------------------------------------------------------
__global__ __launch_bounds__(256) void gather_kernel(
    const float* __restrict__ vert,   // [NVERT, 3]
    float* __restrict__ out)          // [NVERT, NC]
{
    int i = blockIdx.x * blockDim.x + threadIdx.x;
    if (i >= NVERT) return;

    float vx = vert[3 * i + 0];
    float vy = vert[3 * i + 1];
    float vz = vert[3 * i + 2];

    vx = fminf(fmaxf(vx, EPSV), (float)D1 - 1.0f - EPSV);
    vy = fminf(fmaxf(vy, EPSV), (float)D2 - 1.0f - EPSV);
    vz = fminf(fmaxf(vz, EPSV), (float)D3 - 1.0f - EPSV);

    float fx = floorf(vx), fy = floorf(vy), fz = floorf(vz);
    float ux = vx - fx, uy = vy - fy, uz = vz - fz;
    int x0 = (int)fx, y0 = (int)fy, z0 = (int)fz;

    float oux = 1.0f - ux;
    float ouy = 1.0f - uy;
    float ouz = 1.0f - uz;

    // Per corner-pair weights, z-blend folded in:
    //   res[c] += w * (ouz * V[z0][c] + uz * V[z1][c])
    float w00 = oux * ouy;
    float w01 = oux * uy;
    float w10 = ux  * ouy;
    float w11 = ux  * uy;

    const float4* V = reinterpret_cast<const float4*>(g_volT);

    // float4-unit offsets: each (x,y,z) voxel is 16 floats = 4 float4;
    // corner-pair block = 8 float4 (z0 then z1), 64B-aligned.
    long b00 = (((long)x0 * D2 + y0) * D3 + z0) * 4;
    long b01 = b00 + (long)D3 * 4;            // y+1
    long b10 = b00 + (long)D2 * D3 * 4;       // x+1
    long b11 = b10 + (long)D3 * 4;            // x+1, y+1

    float res[NC];
    #pragma unroll
    for (int c = 0; c < NC; c++) res[c] = 0.0f;

    long bases[4] = {b00, b01, b10, b11};
    float ws[4]   = {w00, w01, w10, w11};

    #pragma unroll
    for (int k = 0; k < 4; k++) {
        long b = bases[k];
        float wz0 = ws[k] * ouz;
        float wz1 = ws[k] * uz;
        #pragma unroll
        for (int j = 0; j < 4; j++) {
            float4 a = __ldg(V + b + j);       // z0, channels 4j..4j+3
            float4 q = __ldg(V + b + 4 + j);   // z1, channels 4j..4j+3
            res[4 * j + 0] += wz0 * a.x + wz1 * q.x;
            res[4 * j + 1] += wz0 * a.y + wz1 * q.y;
            res[4 * j + 2] += wz0 * a.z + wz1 * q.z;
            res[4 * j + 3] += wz0 * a.w + wz1 * q.w;
        }
    }

    float4* o4 = reinterpret_cast<float4*>(out + (long)i * NC);
    o4[0] = make_float4(res[0],  res[1],  res[2],  res[3]);
    o4[1] = make_float4(res[4],  res[5],  res[6],  res[7]);
    o4[2] = make_float4(res[8],  res[9],  res[10], res[11]);
    o4[3] = make_float4(res[12], res[13], res[14], res[15]);
}

extern "C" void kernel_launch(void* const* d_in, const int* in_sizes, int n_in,
                              void* d_out, int out_size) {
    const float* vert = (const float*)d_in[0];  // (1, 300000, 3)
    const float* vol  = (const float*)d_in[1];  // (1, 16, 112, 224, 160)
    float* out = (float*)d_out;                 // (1, 300000, 16)

    transpose_kernel<<<D1 * D2, 256>>>(vol);

    const int threads = 256;
    const int blocks = (NVERT + threads - 1) / threads;
    gather_kernel<<<blocks, threads>>>(vert, out);
}

// round 3
// speedup vs baseline: 1.8544x; 1.5407x over previous
#include <cuda_runtime.h>
#include <cuda_fp16.h>

// Trilinear interpolation, two-phase, fp16 scratch:
//   1) transpose+convert vol (16,112,224,160) f32 channel-major
//      -> g_volT_h (112,224,160,16) fp16 channels-last.
//      Corner-pair (z0,z1) block = 64B contiguous, 32B-aligned.
//   2) gather: one thread per vertex, 4 corner-pairs x 4 uint4 loads,
//      fp32 accumulate, f32 output.

#define D1 112
#define D2 224
#define D3 160
#define NC 16
#define NVERT 300000
#define EPSV 1e-5f

// ~128.5 MB fp16 scratch (static __device__ global — allowed)
__device__ __half g_volT_h[(size_t)D1 * D2 * D3 * NC];

// ---------------- transpose: vol[c][x][y][z] (f32) -> volT[x][y][z][c] (fp16)
// One block per (x,y): slab [16][160] f32 -> [160][16] fp16.
// smem padded stride 161: conflict-free on both phases.
__global__ __launch_bounds__(256) void transpose_kernel(
    const float* __restrict__ vol)
{
    __shared__ float s[NC * (D3 + 1)];

    int xy = blockIdx.x;             // 0 .. D1*D2-1
    const long sC = (long)D1 * D2 * D3;
    long base_in = (long)xy * D3;

    // Phase 1: coalesced f32 reads along z
    for (int idx = threadIdx.x; idx < NC * D3; idx += blockDim.x) {
        int c = idx / D3;
        int z = idx - c * D3;
        s[c * (D3 + 1) + z] = vol[(long)c * sC + base_in + z];
    }
    __syncthreads();

    // Phase 2: coalesced half2 writes, contiguous [z][c]
    __half2* outp = reinterpret_cast<__half2*>(g_volT_h + base_in * NC);
    for (int idx = threadIdx.x; idx < (NC * D3) / 2; idx += blockDim.x) {
        int e = idx * 2;             // element index, c fastest
        int z = e >> 4;
        int c = e & 15;
        float v0 = s[c       * (D3 + 1) + z];
        float v1 = s[(c + 1) * (D3 + 1) + z];
        outp[idx] = __floats2half2_rn(v0, v1);
    }
}

// ---------------- gather ------------------------------------------------------
__device__ __forceinline__ void accum8(float* res, uint4 lo, uint4 hi,
                                       float wz0, float wz1)
{
    const __half2* l = reinterpret_cast<const __half2*>(&lo);
    const __half2* h = reinterpret_cast<const __half2*>(&hi);
    #pragma unroll
    for (int p = 0; p < 4; p++) {
        float2 a = __half22float2(l[p]);   // z0, channels 2p,2p+1
        float2 b = __half22float2(h[p]);   // z1
        res[2 * p + 0] += wz0 * a.x + wz1 * b.x;
        res[2 * p + 1] += wz0 * a.y + wz1 * b.y;
    }
}

__global__ __launch_bounds__(256) void gather_kernel(
    const float* __restrict__ vert,   // [NVERT, 3]
    float* __restrict__ out)          // [NVERT, NC]
{
    int i = blockIdx.x * blockDim.x + threadIdx.x;
    if (i >= NVERT) return;

    float vx = vert[3 * i + 0];
    float vy = vert[3 * i + 1];
    float vz = vert[3 * i + 2];

    vx = fminf(fmaxf(vx, EPSV), (float)D1 - 1.0f - EPSV);
    vy = fminf(fmaxf(vy, EPSV), (float)D2 - 1.0f - EPSV);
    vz = fminf(fmaxf(vz, EPSV), (float)D3 - 1.0f - EPSV);

    float fx = floorf(vx), fy = floorf(vy), fz = floorf(vz);
    float ux = vx - fx, uy = vy - fy, uz = vz - fz;
    int x0 = (int)fx, y0 = (int)fy, z0 = (int)fz;

    float oux = 1.0f - ux;
    float ouy = 1.0f - uy;
    float ouz = 1.0f - uz;

    float w00 = oux * ouy;
    float w01 = oux * uy;
    float w10 = ux  * ouy;
    float w11 = ux  * uy;

    // uint4 units: one voxel = 16 fp16 = 32B = 2 uint4.
    // Corner-pair block (z0,z1) = 4 uint4, contiguous.
    const uint4* V = reinterpret_cast<const uint4*>(g_volT_h);
    long b00 = (((long)x0 * D2 + y0) * D3 + z0) * 2;
    long b01 = b00 + (long)D3 * 2;            // y+1
    long b10 = b00 + (long)D2 * D3 * 2;       // x+1
    long b11 = b10 + (long)D3 * 2;            // x+1,y+1

    float res[NC];
    #pragma unroll
    for (int c = 0; c < NC; c++) res[c] = 0.0f;

    long  bases[4] = {b00, b01, b10, b11};
    float ws[4]    = {w00, w01, w10, w11};

    #pragma unroll
    for (int k = 0; k < 4; k++) {
        long b = bases[k];
        float wz0 = ws[k] * ouz;
        float wz1 = ws[k] * uz;
        uint4 z0a = __ldg(V + b + 0);   // z0, ch 0-7
        uint4 z0b = __ldg(V + b + 1);   // z0, ch 8-15
        uint4 z1a = __ldg(V + b + 2);   // z1, ch 0-7
        uint4 z1b = __ldg(V + b + 3);   // z1, ch 8-15
        accum8(res + 0, z0a, z1a, wz0, wz1);
        accum8(res + 8, z0b, z1b, wz0, wz1);
    }

    float4* o4 = reinterpret_cast<float4*>(out + (long)i * NC);
    o4[0] = make_float4(res[0],  res[1],  res[2],  res[3]);
    o4[1] = make_float4(res[4],  res[5],  res[6],  res[7]);
    o4[2] = make_float4(res[8],  res[9],  res[10], res[11]);
    o4[3] = make_float4(res[12], res[13], res[14], res[15]);
}

extern "C" void kernel_launch(void* const* d_in, const int* in_sizes, int n_in,
                              void* d_out, int out_size) {
    const float* vert = (const float*)d_in[0];  // (1, 300000, 3)
    const float* vol  = (const float*)d_in[1];  // (1, 16, 112, 224, 160)
    float* out = (float*)d_out;                 // (1, 300000, 16)

    transpose_kernel<<<D1 * D2, 256>>>(vol);

    const int threads = 256;
    const int blocks = (NVERT + threads - 1) / threads;
    gather_kernel<<<blocks, threads>>>(vert, out);
}

// round 4
// speedup vs baseline: 2.4844x; 1.3397x over previous
#include <cuda_runtime.h>
#include <cuda_fp16.h>

// Trilinear interpolation, two-phase, fp16 scratch:
//   1) register-based transpose+convert: vol (16,112,224,160) f32 ->
//      g_volT_h (112,224,160,16) fp16 channels-last. Warp handles one
//      (xy, 32-z chunk): 16 coalesced 128B reads, each lane writes its
//      voxel's 16 channels as 2x STG.128. No smem, no syncs.
//   2) gather: one thread per vertex, int32 offsets, 4 corner-pairs x
//      4 uint4 loads, fp32 accumulate.

#define D1 112
#define D2 224
#define D3 160
#define NC 16
#define NVERT 300000
#define EPSV 1e-5f

#define ZCHUNKS (D3 / 32)               // 5
#define NWARPS  (D1 * D2 * ZCHUNKS)     // 125440
#define TWARPS_PER_BLOCK 8

// ~128.5 MB fp16 scratch (static __device__ global — allowed)
__device__ __half g_volT_h[(size_t)D1 * D2 * D3 * NC];

// ---------------- transpose: vol[c][x][y][z] (f32) -> volT[x][y][z][c] (fp16)
__global__ __launch_bounds__(TWARPS_PER_BLOCK * 32) void transpose_kernel(
    const float* __restrict__ vol)
{
    int warp = (blockIdx.x * TWARPS_PER_BLOCK) + (threadIdx.x >> 5);
    if (warp >= NWARPS) return;
    int lane = threadIdx.x & 31;

    int xy = warp / ZCHUNKS;            // 0 .. D1*D2-1
    int zb = warp - xy * ZCHUNKS;       // 0 .. 4

    const int sC = D1 * D2 * D3;        // 4014080 (fits int32)
    int z = zb * 32 + lane;
    int vox = xy * D3 + z;              // voxel linear index

    // 16 independent coalesced loads (one per channel)
    float v[NC];
    #pragma unroll
    for (int c = 0; c < NC; c++)
        v[c] = __ldg(vol + c * sC + vox);

    // pack 16 floats -> 8 half2 -> 2 uint4, one contiguous 32B store/lane
    uint4 o[2];
    unsigned* ow = reinterpret_cast<unsigned*>(o);
    #pragma unroll
    for (int p = 0; p < 8; p++) {
        __half2 h = __floats2half2_rn(v[2 * p], v[2 * p + 1]);
        ow[p] = *reinterpret_cast<unsigned*>(&h);
    }

    uint4* dst = reinterpret_cast<uint4*>(g_volT_h) + vox * 2;
    dst[0] = o[0];
    dst[1] = o[1];
}

// ---------------- gather ------------------------------------------------------
__device__ __forceinline__ void accum8(float* res, uint4 lo, uint4 hi,
                                       float wz0, float wz1)
{
    const __half2* l = reinterpret_cast<const __half2*>(&lo);
    const __half2* h = reinterpret_cast<const __half2*>(&hi);
    #pragma unroll
    for (int p = 0; p < 4; p++) {
        float2 a = __half22float2(l[p]);   // z0, channels 2p,2p+1
        float2 b = __half22float2(h[p]);   // z1
        res[2 * p + 0] += wz0 * a.x + wz1 * b.x;
        res[2 * p + 1] += wz0 * a.y + wz1 * b.y;
    }
}

__global__ __launch_bounds__(256, 6) void gather_kernel(
    const float* __restrict__ vert,   // [NVERT, 3]
    float* __restrict__ out)          // [NVERT, NC]
{
    int i = blockIdx.x * blockDim.x + threadIdx.x;
    if (i >= NVERT) return;

    float vx = vert[3 * i + 0];
    float vy = vert[3 * i + 1];
    float vz = vert[3 * i + 2];

    vx = fminf(fmaxf(vx, EPSV), (float)D1 - 1.0f - EPSV);
    vy = fminf(fmaxf(vy, EPSV), (float)D2 - 1.0f - EPSV);
    vz = fminf(fmaxf(vz, EPSV), (float)D3 - 1.0f - EPSV);

    float fx = floorf(vx), fy = floorf(vy), fz = floorf(vz);
    float ux = vx - fx, uy = vy - fy, uz = vz - fz;
    int x0 = (int)fx, y0 = (int)fy, z0 = (int)fz;

    float oux = 1.0f - ux;
    float ouy = 1.0f - uy;
    float ouz = 1.0f - uz;

    float w00 = oux * ouy;
    float w01 = oux * uy;
    float w10 = ux  * ouy;
    float w11 = ux  * uy;

    // uint4 units: one voxel = 16 fp16 = 32B = 2 uint4.
    // Corner-pair block (z0,z1) = 4 uint4, contiguous. Max index
    // 4014080*2 = 8.03M — int32 is fine.
    const uint4* V = reinterpret_cast<const uint4*>(g_volT_h);
    int b00 = ((x0 * D2 + y0) * D3 + z0) * 2;
    int b01 = b00 + D3 * 2;            // y+1
    int b10 = b00 + D2 * D3 * 2;       // x+1
    int b11 = b10 + D3 * 2;            // x+1,y+1

    float res[NC];
    #pragma unroll
    for (int c = 0; c < NC; c++) res[c] = 0.0f;

    int   bases[4] = {b00, b01, b10, b11};
    float ws[4]    = {w00, w01, w10, w11};

    #pragma unroll
    for (int k = 0; k < 4; k++) {
        int b = bases[k];
        float wz0 = ws[k] * ouz;
        float wz1 = ws[k] * uz;
        uint4 z0a = __ldg(V + b + 0);   // z0, ch 0-7
        uint4 z0b = __ldg(V + b + 1);   // z0, ch 8-15
        uint4 z1a = __ldg(V + b + 2);   // z1, ch 0-7
        uint4 z1b = __ldg(V + b + 3);   // z1, ch 8-15
        accum8(res + 0, z0a, z1a, wz0, wz1);
        accum8(res + 8, z0b, z1b, wz0, wz1);
    }

    float4* o4 = reinterpret_cast<float4*>(out + i * NC);
    o4[0] = make_float4(res[0],  res[1],  res[2],  res[3]);
    o4[1] = make_float4(res[4],  res[5],  res[6],  res[7]);
    o4[2] = make_float4(res[8],  res[9],  res[10], res[11]);
    o4[3] = make_float4(res[12], res[13], res[14], res[15]);
}

extern "C" void kernel_launch(void* const* d_in, const int* in_sizes, int n_in,
                              void* d_out, int out_size) {
    const float* vert = (const float*)d_in[0];  // (1, 300000, 3)
    const float* vol  = (const float*)d_in[1];  // (1, 16, 112, 224, 160)
    float* out = (float*)d_out;                 // (1, 300000, 16)

    const int tblocks = (NWARPS + TWARPS_PER_BLOCK - 1) / TWARPS_PER_BLOCK;
    transpose_kernel<<<tblocks, TWARPS_PER_BLOCK * 32>>>(vol);

    const int threads = 256;
    const int blocks = (NVERT + threads - 1) / threads;
    gather_kernel<<<blocks, threads>>>(vert, out);
}

// round 5
// speedup vs baseline: 2.7681x; 1.1142x over previous
#include <cuda_runtime.h>
#include <cuda_fp16.h>

// Trilinear interpolation, two-phase, fp16 scratch:
//   1) register transpose+convert: vol (16,112,224,160) f32 ->
//      g_volT_h (112,224,160,16) fp16 channels-last.
//   2) gather: one thread per vertex; ALL 16 corner uint4 loads issued
//      back-to-back (MLP=16) before any accumulation, fp32 accumulate.

#define D1 112
#define D2 224
#define D3 160
#define NC 16
#define NVERT 300000
#define EPSV 1e-5f

#define ZCHUNKS (D3 / 32)               // 5
#define NWARPS  (D1 * D2 * ZCHUNKS)     // 125440
#define TWARPS_PER_BLOCK 8

// ~128.5 MB fp16 scratch (static __device__ global — allowed)
__device__ __half g_volT_h[(size_t)D1 * D2 * D3 * NC];

// ---------------- transpose: vol[c][x][y][z] (f32) -> volT[x][y][z][c] (fp16)
__global__ __launch_bounds__(TWARPS_PER_BLOCK * 32) void transpose_kernel(
    const float* __restrict__ vol)
{
    int warp = (blockIdx.x * TWARPS_PER_BLOCK) + (threadIdx.x >> 5);
    if (warp >= NWARPS) return;
    int lane = threadIdx.x & 31;

    int xy = warp / ZCHUNKS;            // 0 .. D1*D2-1
    int zb = warp - xy * ZCHUNKS;       // 0 .. 4

    const int sC = D1 * D2 * D3;        // 4014080 (fits int32)
    int z = zb * 32 + lane;
    int vox = xy * D3 + z;              // voxel linear index

    // 16 independent coalesced loads (one per channel)
    float v[NC];
    #pragma unroll
    for (int c = 0; c < NC; c++)
        v[c] = __ldg(vol + c * sC + vox);

    // pack 16 floats -> 8 half2 -> 2 uint4, one contiguous 32B store/lane
    uint4 o[2];
    unsigned* ow = reinterpret_cast<unsigned*>(o);
    #pragma unroll
    for (int p = 0; p < 8; p++) {
        __half2 h = __floats2half2_rn(v[2 * p], v[2 * p + 1]);
        ow[p] = *reinterpret_cast<unsigned*>(&h);
    }

    uint4* dst = reinterpret_cast<uint4*>(g_volT_h) + vox * 2;
    dst[0] = o[0];
    dst[1] = o[1];
}

// ---------------- gather ------------------------------------------------------
__device__ __forceinline__ void accum8(float* res, uint4 lo, uint4 hi,
                                       float wz0, float wz1)
{
    const __half2* l = reinterpret_cast<const __half2*>(&lo);
    const __half2* h = reinterpret_cast<const __half2*>(&hi);
    #pragma unroll
    for (int p = 0; p < 4; p++) {
        float2 a = __half22float2(l[p]);   // z0, channels 2p,2p+1
        float2 b = __half22float2(h[p]);   // z1
        res[2 * p + 0] += wz0 * a.x + wz1 * b.x;
        res[2 * p + 1] += wz0 * a.y + wz1 * b.y;
    }
}

__global__ __launch_bounds__(256, 3) void gather_kernel(
    const float* __restrict__ vert,   // [NVERT, 3]
    float* __restrict__ out)          // [NVERT, NC]
{
    int i = blockIdx.x * blockDim.x + threadIdx.x;
    if (i >= NVERT) return;

    float vx = __ldg(vert + 3 * i + 0);
    float vy = __ldg(vert + 3 * i + 1);
    float vz = __ldg(vert + 3 * i + 2);

    vx = fminf(fmaxf(vx, EPSV), (float)D1 - 1.0f - EPSV);
    vy = fminf(fmaxf(vy, EPSV), (float)D2 - 1.0f - EPSV);
    vz = fminf(fmaxf(vz, EPSV), (float)D3 - 1.0f - EPSV);

    float fx = floorf(vx), fy = floorf(vy), fz = floorf(vz);
    float ux = vx - fx, uy = vy - fy, uz = vz - fz;
    int x0 = (int)fx, y0 = (int)fy, z0 = (int)fz;

    // uint4 units: one voxel = 16 fp16 = 32B = 2 uint4.
    // Corner-pair block (z0,z1) = 4 uint4, contiguous. Max index 8.03M -> int32.
    const uint4* V = reinterpret_cast<const uint4*>(g_volT_h);
    int b00 = ((x0 * D2 + y0) * D3 + z0) * 2;
    int b01 = b00 + D3 * 2;            // y+1
    int b10 = b00 + D2 * D3 * 2;       // x+1
    int b11 = b10 + D3 * 2;            // x+1,y+1

    // ---- issue ALL 16 loads back-to-back: MLP = 16 ----
    uint4 r[16];
    #pragma unroll
    for (int j = 0; j < 4; j++) r[0  + j] = __ldg(V + b00 + j);
    #pragma unroll
    for (int j = 0; j < 4; j++) r[4  + j] = __ldg(V + b01 + j);
    #pragma unroll
    for (int j = 0; j < 4; j++) r[8  + j] = __ldg(V + b10 + j);
    #pragma unroll
    for (int j = 0; j < 4; j++) r[12 + j] = __ldg(V + b11 + j);

    float oux = 1.0f - ux;
    float ouy = 1.0f - uy;
    float ouz = 1.0f - uz;

    float ws[4];
    ws[0] = oux * ouy;   // (x0,y0)
    ws[1] = oux * uy;    // (x0,y1)
    ws[2] = ux  * ouy;   // (x1,y0)
    ws[3] = ux  * uy;    // (x1,y1)

    float res[NC];
    #pragma unroll
    for (int c = 0; c < NC; c++) res[c] = 0.0f;

    #pragma unroll
    for (int k = 0; k < 4; k++) {
        float wz0 = ws[k] * ouz;
        float wz1 = ws[k] * uz;
        // r[4k+0], r[4k+1] = z0 ch0-7, ch8-15; r[4k+2], r[4k+3] = z1
        accum8(res + 0, r[4 * k + 0], r[4 * k + 2], wz0, wz1);
        accum8(res + 8, r[4 * k + 1], r[4 * k + 3], wz0, wz1);
    }

    float4* o4 = reinterpret_cast<float4*>(out + i * NC);
    o4[0] = make_float4(res[0],  res[1],  res[2],  res[3]);
    o4[1] = make_float4(res[4],  res[5],  res[6],  res[7]);
    o4[2] = make_float4(res[8],  res[9],  res[10], res[11]);
    o4[3] = make_float4(res[12], res[13], res[14], res[15]);
}

extern "C" void kernel_launch(void* const* d_in, const int* in_sizes, int n_in,
                              void* d_out, int out_size) {
    const float* vert = (const float*)d_in[0];  // (1, 300000, 3)
    const float* vol  = (const float*)d_in[1];  // (1, 16, 112, 224, 160)
    float* out = (float*)d_out;                 // (1, 300000, 16)

    const int tblocks = (NWARPS + TWARPS_PER_BLOCK - 1) / TWARPS_PER_BLOCK;
    transpose_kernel<<<tblocks, TWARPS_PER_BLOCK * 32>>>(vol);

    const int threads = 256;
    const int blocks = (NVERT + threads - 1) / threads;
    gather_kernel<<<blocks, threads>>>(vert, out);
}